// round 4
// baseline (speedup 1.0000x reference)
#include <cuda_runtime.h>
#include <cstdint>

// Problem shapes (fixed by reference setup_inputs)
#define NT    64     // timesteps
#define NB    128    // batch
#define NF    4096   // input features = HC * SPL1
#define NH    2048   // hidden size H1 (= SPL1)
#define NOC   4      // output channels
#define NSPL2 512    // H1 / NOC
#define NOUT  10

// LIF constants (exactly the f32 values JAX's weak-typed doubles round to)
#define K_MEM 0.1f   // DT * TAU_MEM_INV
#define K_SYN 0.8f   // 1 - DT * TAU_SYN_INV
#define V_TH  1.0f

// Precomputed feedforward hidden currents: [t][b][c*2048 + h], 134 MB scratch
__device__ float g_cur[(size_t)NT * NB * NF];

// ---------------------------------------------------------------------------
// Kernel 1: fp32 tiled GEMM.
//   g_cur[(t*NB+b)*NF + c*NH + n] = sum_k x[(t*NB+b)*NF + c*NH + k] * W[c][k][n]
// M = NT*NB = 8192 rows; per channel N = 2048, K = 2048.
// BM=BN=128, BK=16, 256 threads, 8x8 register tile, double-buffered smem.
// ---------------------------------------------------------------------------
__global__ void __launch_bounds__(256, 2)
hidden_gemm_kernel(const float* __restrict__ X, const float* __restrict__ W) {
    const int c  = blockIdx.z;
    const int m0 = blockIdx.y * 128;
    const int n0 = blockIdx.x * 128;

    __shared__ float As[2][16][132];   // [k][m], 132 pad keeps float4 rows aligned
    __shared__ float Bs[2][16][128];   // [k][n]

    const int tid  = threadIdx.x;
    const int tx   = tid & 15;         // n sub-tile
    const int ty   = tid >> 4;         // m sub-tile
    const int aRow = tid >> 2;         // 0..63
    const int aCol = (tid & 3) << 2;   // 0,4,8,12 (k)
    const int bRow = tid >> 5;         // 0..7 (k)
    const int bCol = (tid & 31) << 2;  // 0..124 (n)

    const float* aPtr = X + (size_t)(m0 + aRow) * NF + (size_t)c * NH + aCol;
    const float* bPtr = W + ((size_t)c * NH + bRow) * NH + n0 + bCol;
    float*       cPtr = g_cur + (size_t)(m0 + ty * 8) * NF + (size_t)c * NH + n0 + tx * 8;

    float acc[8][8];
#pragma unroll
    for (int i = 0; i < 8; i++)
#pragma unroll
        for (int j = 0; j < 8; j++) acc[i][j] = 0.f;

    // Prologue: k-tile 0 -> buffer 0
    {
        float4 a0 = *(const float4*)(aPtr);
        float4 a1 = *(const float4*)(aPtr + (size_t)64 * NF);
        float4 b0 = *(const float4*)(bPtr);
        float4 b1 = *(const float4*)(bPtr + (size_t)8 * NH);
        As[0][aCol + 0][aRow] = a0.x; As[0][aCol + 1][aRow] = a0.y;
        As[0][aCol + 2][aRow] = a0.z; As[0][aCol + 3][aRow] = a0.w;
        As[0][aCol + 0][aRow + 64] = a1.x; As[0][aCol + 1][aRow + 64] = a1.y;
        As[0][aCol + 2][aRow + 64] = a1.z; As[0][aCol + 3][aRow + 64] = a1.w;
        *(float4*)&Bs[0][bRow][bCol]     = b0;
        *(float4*)&Bs[0][bRow + 8][bCol] = b1;
    }
    __syncthreads();

    int buf = 0;
    const int KT = NH / 16;   // 128 k-tiles
    for (int kt = 0; kt < KT; ++kt) {
        float4 a0, a1, b0, b1;
        const bool pre = (kt + 1 < KT);
        if (pre) {
            const int k0 = (kt + 1) * 16;
            a0 = *(const float4*)(aPtr + k0);
            a1 = *(const float4*)(aPtr + (size_t)64 * NF + k0);
            b0 = *(const float4*)(bPtr + (size_t)k0 * NH);
            b1 = *(const float4*)(bPtr + (size_t)(k0 + 8) * NH);
        }
#pragma unroll
        for (int kk = 0; kk < 16; ++kk) {
            float4 af0 = *(const float4*)&As[buf][kk][ty * 8];
            float4 af1 = *(const float4*)&As[buf][kk][ty * 8 + 4];
            float4 bf0 = *(const float4*)&Bs[buf][kk][tx * 8];
            float4 bf1 = *(const float4*)&Bs[buf][kk][tx * 8 + 4];
            float a[8]  = {af0.x, af0.y, af0.z, af0.w, af1.x, af1.y, af1.z, af1.w};
            float bb[8] = {bf0.x, bf0.y, bf0.z, bf0.w, bf1.x, bf1.y, bf1.z, bf1.w};
#pragma unroll
            for (int i = 0; i < 8; i++)
#pragma unroll
                for (int j = 0; j < 8; j++)
                    acc[i][j] = fmaf(a[i], bb[j], acc[i][j]);
        }
        if (pre) {
            const int nb = buf ^ 1;
            As[nb][aCol + 0][aRow] = a0.x; As[nb][aCol + 1][aRow] = a0.y;
            As[nb][aCol + 2][aRow] = a0.z; As[nb][aCol + 3][aRow] = a0.w;
            As[nb][aCol + 0][aRow + 64] = a1.x; As[nb][aCol + 1][aRow + 64] = a1.y;
            As[nb][aCol + 2][aRow + 64] = a1.z; As[nb][aCol + 3][aRow + 64] = a1.w;
            *(float4*)&Bs[nb][bRow][bCol]     = b0;
            *(float4*)&Bs[nb][bRow + 8][bCol] = b1;
        }
        __syncthreads();
        buf ^= 1;
    }

#pragma unroll
    for (int i = 0; i < 8; i++) {
        float4 v0 = make_float4(acc[i][0], acc[i][1], acc[i][2], acc[i][3]);
        float4 v1 = make_float4(acc[i][4], acc[i][5], acc[i][6], acc[i][7]);
        float* cp = cPtr + (size_t)i * NF;
        *(float4*)(cp)     = v0;
        *(float4*)(cp + 4) = v1;
    }
}

// ---------------------------------------------------------------------------
// Kernel 2: persistent per-sample recurrence. 128 blocks (one per batch
// sample) x 512 threads. Thread tid owns h = 4*tid..4*tid+3 for BOTH hidden
// dendritic channels plus the matching somatic neurons; all LIF state AND
// the thread's 4x10 slice of w_out live in registers. Only 800 B of static
// smem (cross-warp reduction scratch) — no dynamic smem, no attribute calls.
// ---------------------------------------------------------------------------
__global__ void __launch_bounds__(512, 1)
recur_kernel(const float* __restrict__ w_out, float* __restrict__ out) {
    __shared__ float wsum[16 * NOUT];   // per-warp partial cur_o
    __shared__ float so[NOC * NOUT];    // output dendritic spikes

    const int b    = blockIdx.x;
    const int tid  = threadIdx.x;
    const int lane = tid & 31;
    const int warp = tid >> 5;

    // Output channel of this thread's somatic neurons h = 4*tid..4*tid+3
    // (a 4-run never crosses a 512 boundary, so one channel per thread).
    const int myc  = tid >> 7;
    const int irow = (tid << 2) & 511;

    // Preload this thread's w_out rows into registers: wr[j][o], reused 64x.
    float wr[4][NOUT];
#pragma unroll
    for (int j = 0; j < 4; j++)
#pragma unroll
        for (int o = 0; o < NOUT; o++)
            wr[j][o] = __ldg(&w_out[((size_t)myc * NSPL2 + irow + j) * NOUT + o]);

    // Register state (all zero-init, matching reference carry0)
    float vd0[4] = {0, 0, 0, 0}, id0v[4] = {0, 0, 0, 0};   // dendritic ch 0
    float vd1[4] = {0, 0, 0, 0}, id1v[4] = {0, 0, 0, 0};   // dendritic ch 1
    float vsh[4] = {0, 0, 0, 0}, ish[4]  = {0, 0, 0, 0};   // somatic
    float vdo = 0.f, ido = 0.f;                            // output dendritic (tid<40)
    float vso = 0.f, iso = 0.f;                            // readout LI (tid<10)

    const float* curp = g_cur + (size_t)b * NF + (tid << 2);

    // Prologue load of t=0 currents
    float4 c0 = *(const float4*)(curp);
    float4 c1 = *(const float4*)(curp + NH);

    const int oc = tid / 10;         // output-stage mapping (tid < 40)
    const int oo = tid - oc * 10;

    for (int t = 0; t < NT; ++t) {
        // Prefetch next timestep's currents
        float4 n0, n1;
        if (t + 1 < NT) {
            const float* p = curp + (size_t)(t + 1) * NB * NF;
            n0 = *(const float4*)(p);
            n1 = *(const float4*)(p + NH);
        }

        const float cu0[4] = {c0.x, c0.y, c0.z, c0.w};
        const float cu1[4] = {c1.x, c1.y, c1.z, c1.w};

        float acc[NOUT];
#pragma unroll
        for (int o = 0; o < NOUT; o++) acc[o] = 0.f;

#pragma unroll
        for (int j = 0; j < 4; j++) {
            float sd = 0.f;
            {   // hidden dendritic channel 0
                const float v = vd0[j], i = id0v[j];
                const float vdec = v + K_MEM * (i - v);
                sd += (vdec > V_TH) ? 1.f : 0.f;
                vd0[j]  = (vdec > V_TH) ? 0.f : vdec;
                id0v[j] = i * K_SYN + cu0[j];
            }
            {   // hidden dendritic channel 1
                const float v = vd1[j], i = id1v[j];
                const float vdec = v + K_MEM * (i - v);
                sd += (vdec > V_TH) ? 1.f : 0.f;
                vd1[j]  = (vdec > V_TH) ? 0.f : vdec;
                id1v[j] = i * K_SYN + cu1[j];
            }
            {   // somatic LIF (input = s_d.sum, an exact small integer)
                const float v = vsh[j], i = ish[j];
                const float vdec = v + K_MEM * (i - v);
                const bool  z = (vdec > V_TH);
                vsh[j] = z ? 0.f : vdec;
                ish[j] = i * K_SYN + sd;
                if (z) {
#pragma unroll
                    for (int o = 0; o < NOUT; o++) acc[o] += wr[j][o];
                }
            }
        }

        // Warp reduction of acc[10]; warps 0-3 cover output channel 0, etc.
#pragma unroll
        for (int o = 0; o < NOUT; o++) {
            float v = acc[o];
            v += __shfl_xor_sync(0xffffffffu, v, 16);
            v += __shfl_xor_sync(0xffffffffu, v, 8);
            v += __shfl_xor_sync(0xffffffffu, v, 4);
            v += __shfl_xor_sync(0xffffffffu, v, 2);
            v += __shfl_xor_sync(0xffffffffu, v, 1);
            acc[o] = v;
        }
        if (lane == 0) {
#pragma unroll
            for (int o = 0; o < NOUT; o++) wsum[warp * NOUT + o] = acc[o];
        }
        __syncthreads();

        // Output dendritic LIF: 40 threads (oc = tid/10, oo = tid%10)
        if (tid < NOC * NOUT) {
            const float cur = wsum[(4 * oc + 0) * NOUT + oo]
                            + wsum[(4 * oc + 1) * NOUT + oo]
                            + wsum[(4 * oc + 2) * NOUT + oo]
                            + wsum[(4 * oc + 3) * NOUT + oo];
            const float vdec = vdo + K_MEM * (ido - vdo);
            const bool  z = (vdec > V_TH);
            vdo = z ? 0.f : vdec;
            ido = ido * K_SYN + cur;
            so[tid] = z ? 1.f : 0.f;
        }
        __syncthreads();

        // Readout LI: 10 threads; voltage uses OLD iso, matching li_step
        if (tid < NOUT) {
            const float ssum = so[tid] + so[tid + 10] + so[tid + 20] + so[tid + 30];
            const float vnew = vso + K_MEM * (iso - vso);
            iso = iso * K_SYN + ssum;
            vso = vnew;
            out[((size_t)t * NB + b) * NOUT + tid] = vnew;
        }
        __syncthreads();   // protect wsum/so before next iteration

        if (t + 1 < NT) { c0 = n0; c1 = n1; }
    }
}

// ---------------------------------------------------------------------------
extern "C" void kernel_launch(void* const* d_in, const int* in_sizes, int n_in,
                              void* d_out, int out_size) {
    // Bind inputs by element count (robust to metadata ordering):
    //   x: 64*128*4096 = 33554432, w_hidden: 2*2048*2048 = 8388608,
    //   w_out: 4*512*10 = 20480
    const float* x  = nullptr;
    const float* wh = nullptr;
    const float* wo = nullptr;
    for (int i = 0; i < n_in; ++i) {
        if (in_sizes[i] == 33554432)     x  = (const float*)d_in[i];
        else if (in_sizes[i] == 8388608) wh = (const float*)d_in[i];
        else if (in_sizes[i] == 20480)   wo = (const float*)d_in[i];
    }
    float* out = (float*)d_out;   // [64,128,10] float32

    // Feedforward GEMM for all timesteps: grid (N/128=16, M/128=64, channels=2)
    dim3 g(NH / 128, (NT * NB) / 128, 2);
    hidden_gemm_kernel<<<g, 256>>>(x, wh);

    // Persistent recurrence, one block per batch sample
    recur_kernel<<<NB, 512>>>(wo, out);
}

// round 7
// speedup vs baseline: 1.2692x; 1.2692x over previous
#include <cuda_runtime.h>
#include <cstdint>

// ---------------- problem shapes ----------------
#define NT    64
#define NB    128
#define NF    4096
#define NH    2048
#define NOC   4
#define NSPL2 512
#define NOUT  10

#define K_MEM 0.1f
#define K_SYN 0.8f
#define V_TH  1.0f

typedef unsigned long long u64;

// Precomputed feedforward hidden currents: [t][b][c*2048 + h]
__device__ float g_cur[(size_t)NT * NB * NF];

// ---------------- packed f32x2 helpers (sm_100 baseline PTX) ----------------
__device__ __forceinline__ u64 pk2(float lo, float hi) {
    u64 r;
    asm("mov.b64 %0, {%1, %2};" : "=l"(r) : "f"(lo), "f"(hi));
    return r;
}
__device__ __forceinline__ void upk2(u64 v, float& lo, float& hi) {
    asm("mov.b64 {%0, %1}, %2;" : "=f"(lo), "=f"(hi) : "l"(v));
}
__device__ __forceinline__ void fma2(u64& d, u64 a, u64 b) {
    asm("fma.rn.f32x2 %0, %1, %2, %0;" : "+l"(d) : "l"(a), "l"(b));
}

// ---------------------------------------------------------------------------
// Kernel 1: fp32 tiled GEMM with packed f32x2 FMAs.
//   g_cur[(t*NB+b)*NF + c*NH + n] = sum_k x[...k] * W[c][k][n]
// M = 8192 rows/channel, N = 2048, K = 2048. BM=BN=128, BK=16, 256 threads,
// 8x8 register tile (as 8x4 packed pairs), double-buffered smem.
// Warp = 8x4 thread tile (8 m-threads x 4 n-threads) to minimize crossbar.
// ---------------------------------------------------------------------------
__global__ void __launch_bounds__(256, 2)
hidden_gemm_kernel(const float* __restrict__ X, const float* __restrict__ W) {
    const int c  = blockIdx.z;
    const int m0 = blockIdx.y * 128;
    const int n0 = blockIdx.x * 128;

    __shared__ float As[2][16][132];   // [k][m]
    __shared__ float Bs[2][16][128];   // [k][n]

    const int tid  = threadIdx.x;
    const int warp = tid >> 5;
    const int lane = tid & 31;

    // 16x16 thread grid; warp covers 8 rows x 4 cols of thread tiles
    const int trow = (warp & 1) * 8 + (lane >> 2);   // 0..15
    const int tcol = (warp >> 1) * 4 + (lane & 3);   // 0..15

    const int aRow = tid >> 2;         // 0..63   (gmem A loader)
    const int aCol = (tid & 3) << 2;   // 0,4,8,12
    const int bRow = tid >> 5;         // 0..7    (gmem B loader)
    const int bCol = (tid & 31) << 2;  // 0..124

    const float* aPtr = X + (size_t)(m0 + aRow) * NF + (size_t)c * NH + aCol;
    const float* bPtr = W + ((size_t)c * NH + bRow) * NH + n0 + bCol;
    float*       cPtr = g_cur + (size_t)(m0 + trow * 8) * NF + (size_t)c * NH
                              + n0 + tcol * 8;

    // 8 m-rows x 4 packed n-pairs (= 8x8 scalar tile)
    u64 acc[8][4];
#pragma unroll
    for (int i = 0; i < 8; i++)
#pragma unroll
        for (int j = 0; j < 4; j++) acc[i][j] = 0ull;

    // Prologue: k-tile 0 -> buffer 0
    {
        float4 a0 = *(const float4*)(aPtr);
        float4 a1 = *(const float4*)(aPtr + (size_t)64 * NF);
        float4 b0 = *(const float4*)(bPtr);
        float4 b1 = *(const float4*)(bPtr + (size_t)8 * NH);
        As[0][aCol + 0][aRow] = a0.x; As[0][aCol + 1][aRow] = a0.y;
        As[0][aCol + 2][aRow] = a0.z; As[0][aCol + 3][aRow] = a0.w;
        As[0][aCol + 0][aRow + 64] = a1.x; As[0][aCol + 1][aRow + 64] = a1.y;
        As[0][aCol + 2][aRow + 64] = a1.z; As[0][aCol + 3][aRow + 64] = a1.w;
        *(float4*)&Bs[0][bRow][bCol]     = b0;
        *(float4*)&Bs[0][bRow + 8][bCol] = b1;
    }
    __syncthreads();

    int buf = 0;
    const int KT = NH / 16;   // 128 k-tiles
    for (int kt = 0; kt < KT; ++kt) {
        float4 a0, a1, b0, b1;
        const bool pre = (kt + 1 < KT);
        if (pre) {
            const int k0 = (kt + 1) * 16;
            a0 = *(const float4*)(aPtr + k0);
            a1 = *(const float4*)(aPtr + (size_t)64 * NF + k0);
            b0 = *(const float4*)(bPtr + (size_t)k0 * NH);
            b1 = *(const float4*)(bPtr + (size_t)(k0 + 8) * NH);
        }
#pragma unroll
        for (int kk = 0; kk < 16; ++kk) {
            float4 af0 = *(const float4*)&As[buf][kk][trow * 8];
            float4 af1 = *(const float4*)&As[buf][kk][trow * 8 + 4];
            float4 bf0 = *(const float4*)&Bs[buf][kk][tcol * 8];
            float4 bf1 = *(const float4*)&Bs[buf][kk][tcol * 8 + 4];
            u64 b2[4];
            b2[0] = pk2(bf0.x, bf0.y);
            b2[1] = pk2(bf0.z, bf0.w);
            b2[2] = pk2(bf1.x, bf1.y);
            b2[3] = pk2(bf1.z, bf1.w);
            const float a[8] = {af0.x, af0.y, af0.z, af0.w,
                                af1.x, af1.y, af1.z, af1.w};
#pragma unroll
            for (int i = 0; i < 8; i++) {
                const u64 a2 = pk2(a[i], a[i]);
#pragma unroll
                for (int j = 0; j < 4; j++) fma2(acc[i][j], a2, b2[j]);
            }
        }
        if (pre) {
            const int nb = buf ^ 1;
            As[nb][aCol + 0][aRow] = a0.x; As[nb][aCol + 1][aRow] = a0.y;
            As[nb][aCol + 2][aRow] = a0.z; As[nb][aCol + 3][aRow] = a0.w;
            As[nb][aCol + 0][aRow + 64] = a1.x; As[nb][aCol + 1][aRow + 64] = a1.y;
            As[nb][aCol + 2][aRow + 64] = a1.z; As[nb][aCol + 3][aRow + 64] = a1.w;
            *(float4*)&Bs[nb][bRow][bCol]     = b0;
            *(float4*)&Bs[nb][bRow + 8][bCol] = b1;
        }
        __syncthreads();
        buf ^= 1;
    }

    // Epilogue: unpack pairs, store 8 floats per row as two float4s
#pragma unroll
    for (int i = 0; i < 8; i++) {
        float4 v0, v1;
        upk2(acc[i][0], v0.x, v0.y);
        upk2(acc[i][1], v0.z, v0.w);
        upk2(acc[i][2], v1.x, v1.y);
        upk2(acc[i][3], v1.z, v1.w);
        float* cp = cPtr + (size_t)i * NF;
        *(float4*)(cp)     = v0;
        *(float4*)(cp + 4) = v1;
    }
}

// ---------------------------------------------------------------------------
// Kernel 2: persistent per-sample recurrence (identical to R4 passing
// version: 128 blocks x 512 threads, all state + w_out slice in registers).
// ---------------------------------------------------------------------------
__global__ void __launch_bounds__(512, 1)
recur_kernel(const float* __restrict__ w_out, float* __restrict__ out) {
    __shared__ float wsum[16 * NOUT];
    __shared__ float so[NOC * NOUT];

    const int b    = blockIdx.x;
    const int tid  = threadIdx.x;
    const int lane = tid & 31;
    const int warp = tid >> 5;

    const int myc  = tid >> 7;
    const int irow = (tid << 2) & 511;

    float wr[4][NOUT];
#pragma unroll
    for (int j = 0; j < 4; j++)
#pragma unroll
        for (int o = 0; o < NOUT; o++)
            wr[j][o] = __ldg(&w_out[((size_t)myc * NSPL2 + irow + j) * NOUT + o]);

    float vd0[4] = {0, 0, 0, 0}, id0v[4] = {0, 0, 0, 0};
    float vd1[4] = {0, 0, 0, 0}, id1v[4] = {0, 0, 0, 0};
    float vsh[4] = {0, 0, 0, 0}, ish[4]  = {0, 0, 0, 0};
    float vdo = 0.f, ido = 0.f;
    float vso = 0.f, iso = 0.f;

    const float* curp = g_cur + (size_t)b * NF + (tid << 2);

    float4 c0 = *(const float4*)(curp);
    float4 c1 = *(const float4*)(curp + NH);

    const int oc = tid / 10;
    const int oo = tid - oc * 10;

    for (int t = 0; t < NT; ++t) {
        float4 n0v, n1v;
        if (t + 1 < NT) {
            const float* p = curp + (size_t)(t + 1) * NB * NF;
            n0v = *(const float4*)(p);
            n1v = *(const float4*)(p + NH);
        }

        const float cu0[4] = {c0.x, c0.y, c0.z, c0.w};
        const float cu1[4] = {c1.x, c1.y, c1.z, c1.w};

        float acc[NOUT];
#pragma unroll
        for (int o = 0; o < NOUT; o++) acc[o] = 0.f;

#pragma unroll
        for (int j = 0; j < 4; j++) {
            float sd = 0.f;
            {
                const float v = vd0[j], i = id0v[j];
                const float vdec = v + K_MEM * (i - v);
                sd += (vdec > V_TH) ? 1.f : 0.f;
                vd0[j]  = (vdec > V_TH) ? 0.f : vdec;
                id0v[j] = i * K_SYN + cu0[j];
            }
            {
                const float v = vd1[j], i = id1v[j];
                const float vdec = v + K_MEM * (i - v);
                sd += (vdec > V_TH) ? 1.f : 0.f;
                vd1[j]  = (vdec > V_TH) ? 0.f : vdec;
                id1v[j] = i * K_SYN + cu1[j];
            }
            {
                const float v = vsh[j], i = ish[j];
                const float vdec = v + K_MEM * (i - v);
                const bool  z = (vdec > V_TH);
                vsh[j] = z ? 0.f : vdec;
                ish[j] = i * K_SYN + sd;
                if (z) {
#pragma unroll
                    for (int o = 0; o < NOUT; o++) acc[o] += wr[j][o];
                }
            }
        }

#pragma unroll
        for (int o = 0; o < NOUT; o++) {
            float v = acc[o];
            v += __shfl_xor_sync(0xffffffffu, v, 16);
            v += __shfl_xor_sync(0xffffffffu, v, 8);
            v += __shfl_xor_sync(0xffffffffu, v, 4);
            v += __shfl_xor_sync(0xffffffffu, v, 2);
            v += __shfl_xor_sync(0xffffffffu, v, 1);
            acc[o] = v;
        }
        if (lane == 0) {
#pragma unroll
            for (int o = 0; o < NOUT; o++) wsum[warp * NOUT + o] = acc[o];
        }
        __syncthreads();

        if (tid < NOC * NOUT) {
            const float cur = wsum[(4 * oc + 0) * NOUT + oo]
                            + wsum[(4 * oc + 1) * NOUT + oo]
                            + wsum[(4 * oc + 2) * NOUT + oo]
                            + wsum[(4 * oc + 3) * NOUT + oo];
            const float vdec = vdo + K_MEM * (ido - vdo);
            const bool  z = (vdec > V_TH);
            vdo = z ? 0.f : vdec;
            ido = ido * K_SYN + cur;
            so[tid] = z ? 1.f : 0.f;
        }
        __syncthreads();

        if (tid < NOUT) {
            const float ssum = so[tid] + so[tid + 10] + so[tid + 20] + so[tid + 30];
            const float vnew = vso + K_MEM * (iso - vso);
            iso = iso * K_SYN + ssum;
            vso = vnew;
            out[((size_t)t * NB + b) * NOUT + tid] = vnew;
        }
        __syncthreads();

        if (t + 1 < NT) { c0 = n0v; c1 = n1v; }
    }
}

// ---------------------------------------------------------------------------
extern "C" void kernel_launch(void* const* d_in, const int* in_sizes, int n_in,
                              void* d_out, int out_size) {
    const float* x  = nullptr;
    const float* wh = nullptr;
    const float* wo = nullptr;
    for (int i = 0; i < n_in; ++i) {
        if (in_sizes[i] == 33554432)     x  = (const float*)d_in[i];
        else if (in_sizes[i] == 8388608) wh = (const float*)d_in[i];
        else if (in_sizes[i] == 20480)   wo = (const float*)d_in[i];
    }
    float* out = (float*)d_out;

    dim3 g(NH / 128, (NT * NB) / 128, 2);
    hidden_gemm_kernel<<<g, 256>>>(x, wh);

    recur_kernel<<<NB, 512>>>(wo, out);
}